// round 11
// baseline (speedup 1.0000x reference)
#include <cuda_runtime.h>
#include <stdint.h>

#define NOPP 3
#define NS   80
#define NA   6
#define DD   512
#define K1B  128     // persistent k1 blocks (<= 148 SMs, one wave)
#define TPB1 256
#define WPITCH 546   // floats; even (float2) and bank-spread
#define MAXR 32      // rows per k1 block (B=4096 / 128)
#define RB2  4       // batch rows per k2 block
#define TPB2 160     // 4 rows x 40 threads; 2 samples per thread

// ---------------- device scratch ----------------
__device__ float g_einv[NOPP * 4096 * NA];
__device__ float g_dist[NOPP * 4096 * NA];
__device__ float g_base[4096 * NA];
__device__ unsigned long long g_entacc;
__device__ unsigned int g_entticket;

// ---------------- threefry2x32, key=(0,42), counter=(0,i); out = x0^x1 ----------------
__device__ __forceinline__ uint32_t tf_fold(uint32_t c1)
{
    const uint32_t KS1 = 42u;
    const uint32_t KS2 = 0x1BD11BDAu ^ 42u;   // ks0 = 0
    uint32_t x0 = 0u, x1 = c1 + KS1;
#define TFR(r) { x0 += x1; x1 = __funnelshift_l(x1, x1, (r)); x1 ^= x0; }
    TFR(13) TFR(15) TFR(26) TFR(6)
    x0 += KS1; x1 += KS2 + 1u;
    TFR(17) TFR(29) TFR(16) TFR(24)
    x0 += KS2; x1 += 2u;
    TFR(13) TFR(15) TFR(26) TFR(6)
    x1 += KS1 + 3u;
    TFR(17) TFR(29) TFR(16) TFR(24)
    x0 += KS1; x1 += KS2 + 4u;
    TFR(13) TFR(15) TFR(26) TFR(6)
    x0 += KS2; x1 += 5u;
#undef TFR
    return x0 ^ x1;
}

// ---------------- k1: persistent GEMM, weights staged coalesced in smem ----------------
__global__ void __launch_bounds__(TPB1) k1(
    const float* __restrict__ x, const float* __restrict__ Wopp,
    const float* __restrict__ bopp, const float* __restrict__ W,
    const float* __restrict__ bias, float* __restrict__ out,
    int B, int out_size)
{
    extern __shared__ float wsm[];           // [24][WPITCH] = 52.4 KB
    __shared__ float vals[MAXR][25];
    __shared__ float entkb[MAXR * 3];

    int tid  = threadIdx.x;
    int warp = tid >> 5;
    int lane = tid & 31;

    // ---- stage full 24-col weight matrix, fully coalesced reads ----
    for (int i = tid; i < NOPP * DD * NA; i += TPB1) {
        int k = i / (DD * NA), r = i % (DD * NA);
        int d = r / NA, a = r % NA;
        wsm[(k * NA + a) * WPITCH + d] = Wopp[i];
    }
    for (int i = tid; i < DD * NA; i += TPB1) {
        int d = i / NA, a = i % NA;
        wsm[(18 + a) * WPITCH + d] = W[i];
    }
    __syncthreads();

    int rows = (B + K1B - 1) / K1B;          // 32 for B=4096
    if (rows > MAXR) rows = MAXR;
    int r0 = blockIdx.x * rows;
    int chunk = (rows + 7) / 8;              // rows per warp (4)

    // ---- GEMM: warp processes its rows in pairs; dual-row FMA per weight LDS ----
    for (int rr = warp * chunk; rr < (warp + 1) * chunk && rr < rows; rr += 2) {
        int bA = r0 + rr, bB = bA + 1;
        bool vA = bA < B;
        bool vB = (rr + 1 < (warp + 1) * chunk) && (rr + 1 < rows) && (bB < B);

        float2 xa[8], xb[8];
        const float2* xpA = reinterpret_cast<const float2*>(x + (size_t)bA * DD);
        const float2* xpB = reinterpret_cast<const float2*>(x + (size_t)bB * DD);
#pragma unroll
        for (int j = 0; j < 8; j++) {
            xa[j] = vA ? xpA[lane + 32 * j] : make_float2(0.f, 0.f);
            xb[j] = vB ? xpB[lane + 32 * j] : make_float2(0.f, 0.f);
        }
        float acc0[24], acc1[24];
#pragma unroll
        for (int c = 0; c < 24; c++) { acc0[c] = 0.f; acc1[c] = 0.f; }
#pragma unroll
        for (int j = 0; j < 8; j++) {
            int dbase = 2 * (lane + 32 * j);
#pragma unroll
            for (int c = 0; c < 24; c++) {
                float2 w2 = *reinterpret_cast<const float2*>(&wsm[c * WPITCH + dbase]);
                acc0[c] = fmaf(xa[j].x, w2.x, fmaf(xa[j].y, w2.y, acc0[c]));
                acc1[c] = fmaf(xb[j].x, w2.x, fmaf(xb[j].y, w2.y, acc1[c]));
            }
        }
#pragma unroll
        for (int off = 16; off; off >>= 1) {
#pragma unroll
            for (int c = 0; c < 24; c++) {
                acc0[c] += __shfl_down_sync(0xffffffffu, acc0[c], off);
                acc1[c] += __shfl_down_sync(0xffffffffu, acc1[c], off);
            }
        }
        if (lane == 0) {
#pragma unroll
            for (int c = 0; c < 24; c++) {
                vals[rr][c] = acc0[c];
                if (rr + 1 < rows) vals[rr + 1][c] = acc1[c];
            }
        }
    }
    __syncthreads();

    // ---- postprocess (strided: FULL coverage of rows*3 and rows*6 tasks) ----
    for (int i = tid; i < rows * 3; i += TPB1) {
        int r = i / 3, k = i % 3, b = r0 + r;
        if (b < B) {
            float l[NA], m = -1e30f;
#pragma unroll
            for (int a = 0; a < NA; a++) {
                l[a] = vals[r][k * 6 + a] + bopp[k * 6 + a];
                m = fmaxf(m, l[a]);
            }
            float e[NA], S = 0.0f;
#pragma unroll
            for (int a = 0; a < NA; a++) { e[a] = expf(l[a] - m); S += e[a]; }
            float logS = logf(S);
            float ent = 0.0f;
            size_t go = ((size_t)k * B + b) * NA;
            size_t distoff = (size_t)B * NA + go;
#pragma unroll
            for (int a = 0; a < NA; a++) {
                float d = e[a] / S;
                g_dist[go + a] = d;
                g_einv[go + a] = expf(-l[a]);
                ent -= d * ((l[a] - m) - logS);
                if (out_size >= B * 24) out[distoff + a] = d;
            }
            entkb[i] = ent;
        } else entkb[i] = 0.0f;
    }
    for (int i = tid; i < rows * 6; i += TPB1) {
        int r = i / 6, a = i % 6, b = r0 + r;
        if (b < B) g_base[b * NA + a] = vals[r][18 + a] + bias[a];
    }
    __syncthreads();

    // ---- entropy: fixed-point atomic + last-block ticket (deterministic, self-resetting) ----
    if (tid == 0) {
        float part = 0.0f;
        for (int i = 0; i < rows * 3; i++) part += entkb[i];
        unsigned long long q =
            (unsigned long long)__double2ll_rn((double)part * 2199023255552.0); // 2^41
        atomicAdd(&g_entacc, q);
        __threadfence();
        unsigned int old = atomicAdd(&g_entticket, 1u);
        if (old == gridDim.x - 1) {
            unsigned long long tot = atomicExch(&g_entacc, 0ull);
            atomicExch(&g_entticket, 0u);
            if (out_size >= B * 24 + 1)
                out[(size_t)B * 24] =
                    (float)((double)tot * (1.0 / 2199023255552.0) / (3.0 * (double)B));
        }
    }
}

// ---------------- k2: sampler, 4 rows x 40 threads, 2 samples/thread (unchanged R9) ----------------
__global__ void __launch_bounds__(TPB2, 6) k2(const float* __restrict__ W,
                                              float* __restrict__ out, int B)
{
    __shared__ float W2s[18 * 8];
    __shared__ float einv_s[RB2][20];
    __shared__ float dist_s[RB2][20];
    __shared__ float base_s[RB2][8];
    __shared__ float pool[7 * TPB2];

    int tid = threadIdx.x;
    int b0  = blockIdx.x * RB2;

    if (tid < 18 * NA) W2s[(tid / 6) * 8 + (tid % 6)] = W[DD * NA + tid];
    for (int i = tid; i < RB2 * 18; i += TPB2) {
        int r = i / 18, q = i % 18, b = b0 + r;
        if (b < B) {
            size_t g = ((size_t)(q / 6) * B + b) * NA + (q % 6);
            einv_s[r][q] = g_einv[g];
            dist_s[r][q] = g_dist[g];
        }
    }
    for (int i = tid; i < RB2 * 6; i += TPB2) {
        int r = i / 6, a = i % 6, b = b0 + r;
        if (b < B) base_s[r][a] = g_base[b * NA + a];
    }
    __syncthreads();

    int r = tid / 40;
    int j = tid - r * 40;
    int b = b0 + r;

    float num[NA] = {0, 0, 0, 0, 0, 0}, den = 0.0f;
    if (b < B) {
        float einv[18];
#pragma unroll
        for (int i = 0; i < 18; i++) einv[i] = einv_s[r][i];

#pragma unroll
        for (int sp = 0; sp < 2; sp++) {
            int s = j + sp * 40;
            float p1 = 1.0f, l[NA];
#pragma unroll
            for (int a = 0; a < NA; a++) l[a] = base_s[r][a];
#pragma unroll
            for (int k = 0; k < 3; k++) {
                uint32_t c0 = (uint32_t)(((k * NS + s) * B + b) * NA);
                uint32_t mp = 0xFFFFFFFFu;
#pragma unroll
                for (int a = 0; a < NA; a++) {  // 6 independent hash chains -> ILP
                    uint32_t bits = tf_fold(c0 + (uint32_t)a);
                    // u = f-1 in [0,1); v = log2(u)*einv (<=0). argmin t*einv
                    // == argmax v; negative-float uint order is reversed, so
                    // umin picks max v; ties pick the lowest action.
                    float f = __uint_as_float((bits >> 9) | 0x3f800000u) - 1.0f;
                    float v = __log2f(f) * einv[k * 6 + a];
                    uint32_t pv = (__float_as_uint(v) & 0xFFFFFFF8u) | (uint32_t)a;
                    mp = (mp < pv) ? mp : pv;
                }
                int amin = (int)(mp & 7u);
                p1 *= dist_s[r][k * 6 + amin];
#pragma unroll
                for (int a = 0; a < NA; a++) l[a] += W2s[(k * 6 + amin) * 8 + a];
            }
            float m = l[0];
#pragma unroll
            for (int a = 1; a < NA; a++) m = fmaxf(m, l[a]);
            float e[NA], S = 0.0f;
#pragma unroll
            for (int a = 0; a < NA; a++) { e[a] = __expf(l[a] - m); S += e[a]; }
            float w = p1 / S;
#pragma unroll
            for (int a = 0; a < NA; a++) num[a] = fmaf(w, e[a], num[a]);
            den += p1;
        }
    }

    // ---- deterministic combine: smem stage + per-row warp tree ----
#pragma unroll
    for (int a = 0; a < NA; a++) pool[a * TPB2 + tid] = num[a];
    pool[6 * TPB2 + tid] = den;
    __syncthreads();

    int warp = tid >> 5, lane = tid & 31;
    if (warp < RB2) {
        int bb = b0 + warp;
        if (bb < B) {
            float res[7];
#pragma unroll
            for (int i = 0; i < 7; i++) {
                int base = i * TPB2 + warp * 40;
                float p = pool[base + lane];
                if (lane < 8) p += pool[base + 32 + lane];
#pragma unroll
                for (int off = 16; off; off >>= 1)
                    p += __shfl_down_sync(0xffffffffu, p, off);
                res[i] = p;
            }
            if (lane == 0) {
                float inv = 1.0f / res[6];
#pragma unroll
                for (int a = 0; a < NA; a++)
                    out[(size_t)bb * NA + a] = res[a] * inv;
            }
        }
    }
}

// ---------------- launch ----------------
extern "C" void kernel_launch(void* const* d_in, const int* in_sizes, int n_in,
                              void* d_out, int out_size)
{
    const float* x    = (const float*)d_in[0];
    const float* Wopp = (const float*)d_in[1];
    const float* bopp = (const float*)d_in[2];
    const float* W    = (const float*)d_in[3];
    const float* bias = (const float*)d_in[4];
    float* out = (float*)d_out;

    int D = in_sizes[1] / (NOPP * NA);   // 512
    int B = in_sizes[0] / D;             // 4096
    if (B > 4096) B = 4096;

    int wbytes = 24 * WPITCH * sizeof(float);   // 52.4 KB dynamic smem
    static int attr_set = 0;
    if (!attr_set) {
        cudaFuncSetAttribute(k1, cudaFuncAttributeMaxDynamicSharedMemorySize, wbytes);
        attr_set = 1;
    }

    k1<<<K1B, TPB1, wbytes>>>(x, Wopp, bopp, W, bias, out, B, out_size);
    k2<<<(B + RB2 - 1) / RB2, TPB2>>>(W, out, B);
}

// round 12
// speedup vs baseline: 1.0395x; 1.0395x over previous
#include <cuda_runtime.h>
#include <stdint.h>

#define NOPP 3
#define NS   80
#define NA   6
#define DD   512
#define RK1  8      // batch rows per k1 block
#define TPB1 256
#define RB2  4      // batch rows per k2 block
#define TPB2 160    // 4 rows x 40 threads; 2 samples per thread

// ---------------- device scratch ----------------
__device__ float g_wt[24 * DD];           // column-major weights (48 KB, L2-resident)
__device__ float g_einv[NOPP * 4096 * NA];
__device__ float g_dist[NOPP * 4096 * NA];
__device__ float g_base[4096 * NA];
__device__ unsigned long long g_entacc;
__device__ unsigned int g_entticket;

// ---------------- threefry2x32, key=(0,42), counter=(0,i); out = x0^x1 ----------------
__device__ __forceinline__ uint32_t tf_fold(uint32_t c1)
{
    const uint32_t KS1 = 42u;
    const uint32_t KS2 = 0x1BD11BDAu ^ 42u;   // ks0 = 0
    uint32_t x0 = 0u, x1 = c1 + KS1;
#define TFR(r) { x0 += x1; x1 = __funnelshift_l(x1, x1, (r)); x1 ^= x0; }
    TFR(13) TFR(15) TFR(26) TFR(6)
    x0 += KS1; x1 += KS2 + 1u;
    TFR(17) TFR(29) TFR(16) TFR(24)
    x0 += KS2; x1 += 2u;
    TFR(13) TFR(15) TFR(26) TFR(6)
    x1 += KS1 + 3u;
    TFR(17) TFR(29) TFR(16) TFR(24)
    x0 += KS1; x1 += KS2 + 4u;
    TFR(13) TFR(15) TFR(26) TFR(6)
    x0 += KS2; x1 += 5u;
#undef TFR
    return x0 ^ x1;
}

// ---------------- kT: transpose weights to column-major scratch (1 block) ----------------
__global__ void __launch_bounds__(1024) kT(const float* __restrict__ Wopp,
                                           const float* __restrict__ W)
{
    int tid = threadIdx.x;
    // Wopp [3][512][6] -> g_wt[(k*6+a)*512 + d]; coalesced reads, scattered writes
    for (int i = tid; i < NOPP * DD * NA; i += 1024) {
        int k = i / (DD * NA), r = i % (DD * NA);
        int d = r / NA, a = r % NA;
        g_wt[(k * NA + a) * DD + d] = Wopp[i];
    }
    // W[:512][6] -> g_wt[(18+a)*512 + d]
    for (int i = tid; i < DD * NA; i += 1024) {
        int d = i / NA, a = i % NA;
        g_wt[(18 + a) * DD + d] = W[i];
    }
}

// ---------------- k1: GEMM (coalesced weights from g_wt) + softmax/einv/dist/base ------
__global__ void __launch_bounds__(TPB1) k1(
    const float* __restrict__ x, const float* __restrict__ bopp,
    const float* __restrict__ bias, float* __restrict__ out,
    int B, int out_size)
{
    __shared__ float xs[RK1 * DD];           // 16 KB
    __shared__ float vals[RK1][25];
    __shared__ float entkb[RK1 * 3];

    int tid  = threadIdx.x;
    int warp = tid >> 5;
    int lane = tid & 31;
    int b0   = blockIdx.x * RK1;

    if (b0 + RK1 <= B) {
        const float4* x4 = reinterpret_cast<const float4*>(x + (size_t)b0 * DD);
        float4* xs4 = reinterpret_cast<float4*>(xs);
        for (int i = tid; i < RK1 * DD / 4; i += TPB1) xs4[i] = x4[i];
    } else {
        for (int i = tid; i < RK1 * DD; i += TPB1) {
            int r = i / DD;
            xs[i] = (b0 + r < B) ? x[(size_t)(b0 + r) * DD + (i % DD)] : 0.0f;
        }
    }

    // per-warp columns 3w..3w+2, fully coalesced from the transposed scratch
    float w0[16], w1[16], w2[16];
    {
        int c = 3 * warp;
        const float* s0 = g_wt + (size_t)(c + 0) * DD + lane;
        const float* s1 = g_wt + (size_t)(c + 1) * DD + lane;
        const float* s2 = g_wt + (size_t)(c + 2) * DD + lane;
#pragma unroll
        for (int j = 0; j < 16; j++) {
            w0[j] = s0[32 * j]; w1[j] = s1[32 * j]; w2[j] = s2[32 * j];
        }
    }
    __syncthreads();

    for (int r = 0; r < RK1; r++) {
        const float* xr = xs + r * DD + lane;
        float a0 = 0.f, a1 = 0.f, a2 = 0.f;
#pragma unroll
        for (int j = 0; j < 16; j++) {
            float xv = xr[32 * j];
            a0 = fmaf(xv, w0[j], a0);
            a1 = fmaf(xv, w1[j], a1);
            a2 = fmaf(xv, w2[j], a2);
        }
#pragma unroll
        for (int off = 16; off; off >>= 1) {
            a0 += __shfl_down_sync(0xffffffffu, a0, off);
            a1 += __shfl_down_sync(0xffffffffu, a1, off);
            a2 += __shfl_down_sync(0xffffffffu, a2, off);
        }
        if (lane == 0) {
            vals[r][3 * warp + 0] = a0;
            vals[r][3 * warp + 1] = a1;
            vals[r][3 * warp + 2] = a2;
        }
    }
    __syncthreads();

    // postprocess (strided loops: full coverage regardless of counts)
    for (int i = tid; i < RK1 * 3; i += TPB1) {
        int r = i / 3, k = i % 3, b = b0 + r;
        if (b < B) {
            float l[NA], m = -1e30f;
#pragma unroll
            for (int a = 0; a < NA; a++) {
                l[a] = vals[r][k * 6 + a] + bopp[k * 6 + a];
                m = fmaxf(m, l[a]);
            }
            float e[NA], S = 0.0f;
#pragma unroll
            for (int a = 0; a < NA; a++) { e[a] = expf(l[a] - m); S += e[a]; }
            float logS = logf(S);
            float ent = 0.0f;
            size_t go = ((size_t)k * B + b) * NA;
            size_t distoff = (size_t)B * NA + go;
#pragma unroll
            for (int a = 0; a < NA; a++) {
                float d = e[a] / S;
                g_dist[go + a] = d;
                g_einv[go + a] = expf(-l[a]);
                ent -= d * ((l[a] - m) - logS);
                if (out_size >= B * 24) out[distoff + a] = d;
            }
            entkb[i] = ent;
        } else entkb[i] = 0.0f;
    }
    for (int i = tid; i < RK1 * 6; i += TPB1) {
        int r = i / 6, a = i % 6, b = b0 + r;
        if (b < B) g_base[b * NA + a] = vals[r][18 + a] + bias[a];
    }
    __syncthreads();

    // entropy: fixed-point atomic + last-block ticket (deterministic, self-resetting)
    if (tid == 0) {
        float part = 0.0f;
        for (int i = 0; i < RK1 * 3; i++) part += entkb[i];
        unsigned long long q =
            (unsigned long long)__double2ll_rn((double)part * 2199023255552.0); // 2^41
        atomicAdd(&g_entacc, q);
        __threadfence();
        unsigned int old = atomicAdd(&g_entticket, 1u);
        if (old == gridDim.x - 1) {
            unsigned long long tot = atomicExch(&g_entacc, 0ull);
            atomicExch(&g_entticket, 0u);
            if (out_size >= B * 24 + 1)
                out[(size_t)B * 24] =
                    (float)((double)tot * (1.0 / 2199023255552.0) / (3.0 * (double)B));
        }
    }
}

// ---------------- k2: sampler, 4 rows x 40 threads, 2 samples/thread ----------------
__global__ void __launch_bounds__(TPB2, 7) k2(const float* __restrict__ W,
                                              float* __restrict__ out, int B)
{
    __shared__ float W2s[18 * 8];
    __shared__ float einv_s[RB2][20];
    __shared__ float dist_s[RB2][20];
    __shared__ float base_s[RB2][8];
    __shared__ float pool[7 * TPB2];

    int tid = threadIdx.x;
    int b0  = blockIdx.x * RB2;

    if (tid < 18 * NA) W2s[(tid / 6) * 8 + (tid % 6)] = W[DD * NA + tid];
    for (int i = tid; i < RB2 * 18; i += TPB2) {
        int r = i / 18, q = i % 18, b = b0 + r;
        if (b < B) {
            size_t g = ((size_t)(q / 6) * B + b) * NA + (q % 6);
            einv_s[r][q] = g_einv[g];
            dist_s[r][q] = g_dist[g];
        }
    }
    for (int i = tid; i < RB2 * 6; i += TPB2) {
        int r = i / 6, a = i % 6, b = b0 + r;
        if (b < B) base_s[r][a] = g_base[b * NA + a];
    }
    __syncthreads();

    int r = tid / 40;
    int j = tid - r * 40;
    int b = b0 + r;

    float num[NA] = {0, 0, 0, 0, 0, 0}, den = 0.0f;
    if (b < B) {
        float einv[18];
#pragma unroll
        for (int i = 0; i < 18; i++) einv[i] = einv_s[r][i];

#pragma unroll
        for (int sp = 0; sp < 2; sp++) {
            int s = j + sp * 40;
            float p1 = 1.0f, l[NA];
#pragma unroll
            for (int a = 0; a < NA; a++) l[a] = base_s[r][a];
#pragma unroll
            for (int k = 0; k < 3; k++) {
                uint32_t c0 = (uint32_t)(((k * NS + s) * B + b) * NA);
                uint32_t mp = 0xFFFFFFFFu;
#pragma unroll
                for (int a = 0; a < NA; a++) {  // 6 independent hash chains -> ILP
                    uint32_t bits = tf_fold(c0 + (uint32_t)a);
                    // u = f-1 in [0,1); v = log2(u)*einv (<=0). argmin t*einv
                    // == argmax v; negative-float uint order is reversed, so
                    // umin picks max v; ties pick the lowest action.
                    float f = __uint_as_float((bits >> 9) | 0x3f800000u) - 1.0f;
                    float v = __log2f(f) * einv[k * 6 + a];
                    uint32_t pv = (__float_as_uint(v) & 0xFFFFFFF8u) | (uint32_t)a;
                    mp = (mp < pv) ? mp : pv;
                }
                int amin = (int)(mp & 7u);
                p1 *= dist_s[r][k * 6 + amin];
#pragma unroll
                for (int a = 0; a < NA; a++) l[a] += W2s[(k * 6 + amin) * 8 + a];
            }
            float m = l[0];
#pragma unroll
            for (int a = 1; a < NA; a++) m = fmaxf(m, l[a]);
            float e[NA], S = 0.0f;
#pragma unroll
            for (int a = 0; a < NA; a++) { e[a] = __expf(l[a] - m); S += e[a]; }
            float w = p1 / S;
#pragma unroll
            for (int a = 0; a < NA; a++) num[a] = fmaf(w, e[a], num[a]);
            den += p1;
        }
    }

    // deterministic combine: smem stage + per-row warp tree
#pragma unroll
    for (int a = 0; a < NA; a++) pool[a * TPB2 + tid] = num[a];
    pool[6 * TPB2 + tid] = den;
    __syncthreads();

    int warp = tid >> 5, lane = tid & 31;
    if (warp < RB2) {
        int bb = b0 + warp;
        if (bb < B) {
            float res[7];
#pragma unroll
            for (int i = 0; i < 7; i++) {
                int base = i * TPB2 + warp * 40;
                float p = pool[base + lane];
                if (lane < 8) p += pool[base + 32 + lane];
#pragma unroll
                for (int off = 16; off; off >>= 1)
                    p += __shfl_down_sync(0xffffffffu, p, off);
                res[i] = p;
            }
            if (lane == 0) {
                float inv = 1.0f / res[6];
#pragma unroll
                for (int a = 0; a < NA; a++)
                    out[(size_t)bb * NA + a] = res[a] * inv;
            }
        }
    }
}

// ---------------- launch ----------------
extern "C" void kernel_launch(void* const* d_in, const int* in_sizes, int n_in,
                              void* d_out, int out_size)
{
    const float* x    = (const float*)d_in[0];
    const float* Wopp = (const float*)d_in[1];
    const float* bopp = (const float*)d_in[2];
    const float* W    = (const float*)d_in[3];
    const float* bias = (const float*)d_in[4];
    float* out = (float*)d_out;

    int D = in_sizes[1] / (NOPP * NA);   // 512
    int B = in_sizes[0] / D;             // 4096
    if (B > 4096) B = 4096;

    kT<<<1, 1024>>>(Wopp, W);
    k1<<<(B + RK1 - 1) / RK1, TPB1>>>(x, bopp, bias, out, B, out_size);
    k2<<<(B + RB2 - 1) / RB2, TPB2>>>(W, out, B);
}

// round 13
// speedup vs baseline: 1.1036x; 1.0616x over previous
#include <cuda_runtime.h>
#include <stdint.h>

#define NOPP 3
#define NS   80
#define NA   6
#define DD   512
#define RK1  8      // batch rows per k1 block
#define TPB1 256
#define RB2  4      // batch rows per k2 block
#define TPB2 160    // 4 rows x 40 threads; 2 samples per thread

// ---------------- device scratch ----------------
__device__ float g_wt[24 * DD];           // column-major weights (48 KB, L2-resident)
__device__ float g_einv[NOPP * 4096 * NA];
__device__ float g_dist[NOPP * 4096 * NA];
__device__ float g_base[4096 * NA];
__device__ unsigned long long g_entacc;
__device__ unsigned int g_entticket;

// ---------------- threefry2x32, key=(0,42), counter=(0,i); out = x0^x1 ----------------
__device__ __forceinline__ uint32_t tf_fold(uint32_t c1)
{
    const uint32_t KS1 = 42u;
    const uint32_t KS2 = 0x1BD11BDAu ^ 42u;   // ks0 = 0
    uint32_t x0 = 0u, x1 = c1 + KS1;
#define TFR(r) { x0 += x1; x1 = __funnelshift_l(x1, x1, (r)); x1 ^= x0; }
    TFR(13) TFR(15) TFR(26) TFR(6)
    x0 += KS1; x1 += KS2 + 1u;
    TFR(17) TFR(29) TFR(16) TFR(24)
    x0 += KS2; x1 += 2u;
    TFR(13) TFR(15) TFR(26) TFR(6)
    x1 += KS1 + 3u;
    TFR(17) TFR(29) TFR(16) TFR(24)
    x0 += KS1; x1 += KS2 + 4u;
    TFR(13) TFR(15) TFR(26) TFR(6)
    x0 += KS2; x1 += 5u;
#undef TFR
    return x0 ^ x1;
}

// ---------------- kT: transpose weights (48 blocks x 256 = 1 elem/thread) -------------
__global__ void __launch_bounds__(256) kT(const float* __restrict__ Wopp,
                                          const float* __restrict__ W)
{
    int i = blockIdx.x * 256 + threadIdx.x;       // 0 .. 12287
    if (i < NOPP * DD * NA) {                     // 9216 Wopp elements
        int k = i / (DD * NA), r = i % (DD * NA);
        int d = r / NA, a = r % NA;
        g_wt[(k * NA + a) * DD + d] = Wopp[i];
    } else {                                      // 3072 W[:512] elements
        int j = i - NOPP * DD * NA;
        int d = j / NA, a = j % NA;
        g_wt[(18 + a) * DD + d] = W[j];
    }
}

// ---------------- k1: GEMM (coalesced weights from g_wt) + softmax/einv/dist/base ------
__global__ void __launch_bounds__(TPB1) k1(
    const float* __restrict__ x, const float* __restrict__ bopp,
    const float* __restrict__ bias, float* __restrict__ out,
    int B, int out_size)
{
    __shared__ float xs[RK1 * DD];           // 16 KB
    __shared__ float vals[RK1][25];
    __shared__ float entkb[RK1 * 3];

    int tid  = threadIdx.x;
    int warp = tid >> 5;
    int lane = tid & 31;
    int b0   = blockIdx.x * RK1;

    if (b0 + RK1 <= B) {
        const float4* x4 = reinterpret_cast<const float4*>(x + (size_t)b0 * DD);
        float4* xs4 = reinterpret_cast<float4*>(xs);
        for (int i = tid; i < RK1 * DD / 4; i += TPB1) xs4[i] = x4[i];
    } else {
        for (int i = tid; i < RK1 * DD; i += TPB1) {
            int r = i / DD;
            xs[i] = (b0 + r < B) ? x[(size_t)(b0 + r) * DD + (i % DD)] : 0.0f;
        }
    }

    // per-warp columns 3w..3w+2, fully coalesced from the transposed scratch
    float w0[16], w1[16], w2[16];
    {
        int c = 3 * warp;
        const float* s0 = g_wt + (size_t)(c + 0) * DD + lane;
        const float* s1 = g_wt + (size_t)(c + 1) * DD + lane;
        const float* s2 = g_wt + (size_t)(c + 2) * DD + lane;
#pragma unroll
        for (int j = 0; j < 16; j++) {
            w0[j] = s0[32 * j]; w1[j] = s1[32 * j]; w2[j] = s2[32 * j];
        }
    }
    __syncthreads();

    for (int r = 0; r < RK1; r++) {
        const float* xr = xs + r * DD + lane;
        float a0 = 0.f, a1 = 0.f, a2 = 0.f;
#pragma unroll
        for (int j = 0; j < 16; j++) {
            float xv = xr[32 * j];
            a0 = fmaf(xv, w0[j], a0);
            a1 = fmaf(xv, w1[j], a1);
            a2 = fmaf(xv, w2[j], a2);
        }
#pragma unroll
        for (int off = 16; off; off >>= 1) {
            a0 += __shfl_down_sync(0xffffffffu, a0, off);
            a1 += __shfl_down_sync(0xffffffffu, a1, off);
            a2 += __shfl_down_sync(0xffffffffu, a2, off);
        }
        if (lane == 0) {
            vals[r][3 * warp + 0] = a0;
            vals[r][3 * warp + 1] = a1;
            vals[r][3 * warp + 2] = a2;
        }
    }
    __syncthreads();

    // postprocess (strided loops: full coverage regardless of counts)
    for (int i = tid; i < RK1 * 3; i += TPB1) {
        int r = i / 3, k = i % 3, b = b0 + r;
        if (b < B) {
            float l[NA], m = -1e30f;
#pragma unroll
            for (int a = 0; a < NA; a++) {
                l[a] = vals[r][k * 6 + a] + bopp[k * 6 + a];
                m = fmaxf(m, l[a]);
            }
            float e[NA], S = 0.0f;
#pragma unroll
            for (int a = 0; a < NA; a++) { e[a] = expf(l[a] - m); S += e[a]; }
            float logS = logf(S);
            float ent = 0.0f;
            size_t go = ((size_t)k * B + b) * NA;
            size_t distoff = (size_t)B * NA + go;
#pragma unroll
            for (int a = 0; a < NA; a++) {
                float d = e[a] / S;
                g_dist[go + a] = d;
                g_einv[go + a] = expf(-l[a]);
                ent -= d * ((l[a] - m) - logS);
                if (out_size >= B * 24) out[distoff + a] = d;
            }
            entkb[i] = ent;
        } else entkb[i] = 0.0f;
    }
    for (int i = tid; i < RK1 * 6; i += TPB1) {
        int r = i / 6, a = i % 6, b = b0 + r;
        if (b < B) g_base[b * NA + a] = vals[r][18 + a] + bias[a];
    }
    __syncthreads();

    // entropy: fixed-point atomic + last-block ticket (deterministic, self-resetting)
    if (tid == 0) {
        float part = 0.0f;
        for (int i = 0; i < RK1 * 3; i++) part += entkb[i];
        unsigned long long q =
            (unsigned long long)__double2ll_rn((double)part * 2199023255552.0); // 2^41
        atomicAdd(&g_entacc, q);
        __threadfence();
        unsigned int old = atomicAdd(&g_entticket, 1u);
        if (old == gridDim.x - 1) {
            unsigned long long tot = atomicExch(&g_entacc, 0ull);
            atomicExch(&g_entticket, 0u);
            if (out_size >= B * 24 + 1)
                out[(size_t)B * 24] =
                    (float)((double)tot * (1.0 / 2199023255552.0) / (3.0 * (double)B));
        }
    }
}

// ---------------- k2: sampler, 4 rows x 40 threads, 2 samples/thread ----------------
__global__ void __launch_bounds__(TPB2, 7) k2(const float* __restrict__ W,
                                              float* __restrict__ out, int B)
{
    __shared__ float W2s[18 * 8];
    __shared__ float einv_s[RB2][20];
    __shared__ float dist_s[RB2][20];
    __shared__ float base_s[RB2][8];
    __shared__ float pool[7 * TPB2];

    int tid = threadIdx.x;
    int b0  = blockIdx.x * RB2;

    if (tid < 18 * NA) W2s[(tid / 6) * 8 + (tid % 6)] = W[DD * NA + tid];
    for (int i = tid; i < RB2 * 18; i += TPB2) {
        int r = i / 18, q = i % 18, b = b0 + r;
        if (b < B) {
            size_t g = ((size_t)(q / 6) * B + b) * NA + (q % 6);
            einv_s[r][q] = g_einv[g];
            dist_s[r][q] = g_dist[g];
        }
    }
    for (int i = tid; i < RB2 * 6; i += TPB2) {
        int r = i / 6, a = i % 6, b = b0 + r;
        if (b < B) base_s[r][a] = g_base[b * NA + a];
    }
    __syncthreads();

    int r = tid / 40;
    int j = tid - r * 40;
    int b = b0 + r;

    float num[NA] = {0, 0, 0, 0, 0, 0}, den = 0.0f;
    if (b < B) {
        float einv[18];
#pragma unroll
        for (int i = 0; i < 18; i++) einv[i] = einv_s[r][i];

#pragma unroll
        for (int sp = 0; sp < 2; sp++) {
            int s = j + sp * 40;
            float p1 = 1.0f, l[NA];
#pragma unroll
            for (int a = 0; a < NA; a++) l[a] = base_s[r][a];
#pragma unroll
            for (int k = 0; k < 3; k++) {
                uint32_t c0 = (uint32_t)(((k * NS + s) * B + b) * NA);
                uint32_t mp = 0xFFFFFFFFu;
#pragma unroll
                for (int a = 0; a < NA; a++) {  // 6 independent hash chains -> ILP
                    uint32_t bits = tf_fold(c0 + (uint32_t)a);
                    // u = f-1 in [0,1); v = log2(u)*einv (<=0). argmin t*einv
                    // == argmax v; negative-float uint order is reversed, so
                    // umin picks max v; ties pick the lowest action.
                    float f = __uint_as_float((bits >> 9) | 0x3f800000u) - 1.0f;
                    float v = __log2f(f) * einv[k * 6 + a];
                    uint32_t pv = (__float_as_uint(v) & 0xFFFFFFF8u) | (uint32_t)a;
                    mp = (mp < pv) ? mp : pv;
                }
                int amin = (int)(mp & 7u);
                p1 *= dist_s[r][k * 6 + amin];
#pragma unroll
                for (int a = 0; a < NA; a++) l[a] += W2s[(k * 6 + amin) * 8 + a];
            }
            float m = l[0];
#pragma unroll
            for (int a = 1; a < NA; a++) m = fmaxf(m, l[a]);
            float e[NA], S = 0.0f;
#pragma unroll
            for (int a = 0; a < NA; a++) { e[a] = __expf(l[a] - m); S += e[a]; }
            float w = p1 / S;
#pragma unroll
            for (int a = 0; a < NA; a++) num[a] = fmaf(w, e[a], num[a]);
            den += p1;
        }
    }

    // deterministic combine: smem stage + per-row warp tree
#pragma unroll
    for (int a = 0; a < NA; a++) pool[a * TPB2 + tid] = num[a];
    pool[6 * TPB2 + tid] = den;
    __syncthreads();

    int warp = tid >> 5, lane = tid & 31;
    if (warp < RB2) {
        int bb = b0 + warp;
        if (bb < B) {
            float res[7];
#pragma unroll
            for (int i = 0; i < 7; i++) {
                int base = i * TPB2 + warp * 40;
                float p = pool[base + lane];
                if (lane < 8) p += pool[base + 32 + lane];
#pragma unroll
                for (int off = 16; off; off >>= 1)
                    p += __shfl_down_sync(0xffffffffu, p, off);
                res[i] = p;
            }
            if (lane == 0) {
                float inv = 1.0f / res[6];
#pragma unroll
                for (int a = 0; a < NA; a++)
                    out[(size_t)bb * NA + a] = res[a] * inv;
            }
        }
    }
}

// ---------------- launch ----------------
extern "C" void kernel_launch(void* const* d_in, const int* in_sizes, int n_in,
                              void* d_out, int out_size)
{
    const float* x    = (const float*)d_in[0];
    const float* Wopp = (const float*)d_in[1];
    const float* bopp = (const float*)d_in[2];
    const float* W    = (const float*)d_in[3];
    const float* bias = (const float*)d_in[4];
    float* out = (float*)d_out;

    int D = in_sizes[1] / (NOPP * NA);   // 512
    int B = in_sizes[0] / D;             // 4096
    if (B > 4096) B = 4096;

    kT<<<48, 256>>>(Wopp, W);            // 12288 threads, 1 element each
    k1<<<(B + RK1 - 1) / RK1, TPB1>>>(x, bopp, bias, out, B, out_size);
    k2<<<(B + RB2 - 1) / RB2, TPB2>>>(W, out, B);
}